// round 17
// baseline (speedup 1.0000x reference)
#include <cuda_runtime.h>
#include <cuda_fp16.h>
#include <math.h>
#include <stdint.h>

#define BB 4
#define CC 64
#define HH 96
#define WW 96
#define NN (HH*WW)      // 9216
#define HP (HH/2)
#define WP (WW/2)
#define MM (HP*WP)      // 2304
#define KK 64

// Scratch (no allocations allowed)
__device__ __align__(16) __half g_xh[BB*NN*KK];   // x hi, [b][n][c]
__device__ __align__(16) __half g_xl[BB*NN*KK];   // x lo, [b][n][c]
__device__ __align__(16) __half g_uh[BB*MM*KK];   // u'=ea*G*xp (fp16), [b][m][d]
__device__ __align__(16) __half g_vh[BB*CC*MM];   // v fp16, [b][c][m]
__device__ __align__(16) float  g_v  [BB*CC*MM];  // pooled x fp32, [b][c][m]
__device__ __align__(16) float  g_c2p[BB*CC*MM];  // pooled c2, [b][c][m]
__device__ __align__(16) float  g_cm [BB*MM];     // ea*(alpha+bb), [b][m]
__device__ __align__(16) float  g_eam[BB*MM];     // ea, [b][m]
__device__ __align__(16) float  g_beta[BB*NN];    // wb . x_n, [b][n]
__device__ __align__(16) float g_G  [64*64];   // Wq^T Wq (symmetric, [c][o])
__device__ __align__(16) float g_W1t[128*64];  // w_ea1 transposed: [c][o]
__device__ float g_wb[64];                     // b_q^T Wq
__device__ float g_bb[1];                      // |b_q|^2

// ---- mma / async helpers --------------------------------------------------
__device__ __forceinline__ void ldm4(uint32_t* r, uint32_t addr) {
    asm volatile("ldmatrix.sync.aligned.m8n8.x4.shared.b16 {%0,%1,%2,%3}, [%4];"
        : "=r"(r[0]), "=r"(r[1]), "=r"(r[2]), "=r"(r[3]) : "r"(addr));
}
__device__ __forceinline__ void mma16(float* d, const uint32_t* a, uint32_t b0, uint32_t b1) {
    asm volatile("mma.sync.aligned.m16n8k16.row.col.f32.f16.f16.f32 "
        "{%0,%1,%2,%3}, {%4,%5,%6,%7}, {%8,%9}, {%0,%1,%2,%3};"
        : "+f"(d[0]), "+f"(d[1]), "+f"(d[2]), "+f"(d[3])
        : "r"(a[0]), "r"(a[1]), "r"(a[2]), "r"(a[3]), "r"(b0), "r"(b1));
}
__device__ __forceinline__ uint32_t smem_u32(const void* p) {
    return (uint32_t)__cvta_generic_to_shared(p);
}
__device__ __forceinline__ uint32_t pack_h2(float lo, float hi) {
    uint32_t r; asm("cvt.rn.f16x2.f32 %0, %1, %2;" : "=r"(r) : "f"(hi), "f"(lo)); return r;
}
__device__ __forceinline__ void cpa16(uint32_t s, const void* g) {
    asm volatile("cp.async.cg.shared.global [%0], [%1], 16;" :: "r"(s), "l"(g));
}
#define CPA_COMMIT() asm volatile("cp.async.commit_group;" ::: "memory")
#define CPA_WAIT0()  asm volatile("cp.async.wait_group 0;"  ::: "memory")

// attn smem layout (bytes). Stage stride 17408 = 17*1024.
#define B_XHI 0                       // [128 r][64 c] f16 (16 KB)
#define B_XLO 16384
#define B_ST(s) (32768 + (s)*17408)   // per-stage: UH +0, VS +8192,
#define ST_UH 0                       //            CM +16384, EAM +16640
#define ST_VS 8192
#define ST_CM 16384
#define ST_EAM 16640
#define B_BETA 67584                  // [128] float
#define ATTN_SMEM_BYTES 68096

// kvea smem layout (float offsets)
#define KV_G   0          // [64 c][64 o]
#define KV_W1T 4096       // [128 c][64 o]
#define KV_XP  12288      // [64 c][32 p]
#define KV_C2P 14336      // [64 c][32 p]
#define KV_EA  16384      // [32]
#define KVEA_SMEM_BYTES  ((16384 + 32) * 4)   // 65664 B -> 2 blocks/SM

// ---------------------------------------------------------------------------
// G0: G = Wq^T Wq, wb = b^T Wq, bb = |b|^2, W1t = w_ea1^T. One block.
// ---------------------------------------------------------------------------
__global__ void __launch_bounds__(256) gmat_kernel(
    const float* __restrict__ w_q, const float* __restrict__ b_q,
    const float* __restrict__ w_ea1)
{
    __shared__ float sW[64*65];
    const int tid = threadIdx.x;
    for (int i = tid; i < 4096; i += 256) sW[(i>>6)*65 + (i&63)] = w_q[i];
    __syncthreads();
    for (int i = tid; i < 4096; i += 256) {
        int c1 = i >> 6, c2 = i & 63;
        float acc = 0.f;
        #pragma unroll 8
        for (int k = 0; k < 64; k++) acc += sW[k*65 + c1] * sW[k*65 + c2];
        g_G[i] = acc;
    }
    for (int i = tid; i < 8192; i += 256) {
        int o = i >> 7, c = i & 127;
        g_W1t[c*64 + o] = w_ea1[i];
    }
    if (tid < 64) {
        float acc = 0.f;
        #pragma unroll 8
        for (int k = 0; k < 64; k++) acc += b_q[k] * sW[k*65 + tid];
        g_wb[tid] = acc;
    }
    if (tid == 0) {
        float acc = 0.f;
        for (int k = 0; k < 64; k++) acc += b_q[k]*b_q[k];
        g_bb[0] = acc;
    }
}

// ---------------------------------------------------------------------------
// P0: 2x2 maxpool of x and c2. Streaming.
// ---------------------------------------------------------------------------
__global__ void __launch_bounds__(256) pool_kernel(
    const float* __restrict__ x, const float* __restrict__ c2)
{
    int idx = blockIdx.x * 256 + threadIdx.x;
    if (idx >= BB*CC*MM) return;
    int m = idx % MM;
    int bc = idx / MM;
    int py = m / WP, px = m % WP;
    int base = (bc*HH + 2*py)*WW + 2*px;
    float2 a0 = *(const float2*)(x + base);
    float2 a1 = *(const float2*)(x + base + WW);
    float vx = fmaxf(fmaxf(a0.x, a0.y), fmaxf(a1.x, a1.y));
    g_v [idx] = vx;
    g_vh[idx] = __float2half_rn(vx);
    float2 b0 = *(const float2*)(c2 + base);
    float2 b1 = *(const float2*)(c2 + base + WW);
    g_c2p[idx] = fmaxf(fmaxf(b0.x, b0.y), fmaxf(b1.x, b1.y));
}

// ---------------------------------------------------------------------------
// P1: transpose+split x -> g_xh/g_xl [b][n][c], beta_n = wb . x_n
// ---------------------------------------------------------------------------
__global__ void __launch_bounds__(256) xsplit_kernel(const float* __restrict__ x)
{
    __shared__ float sX [64*65];
    __shared__ float swb[64];
    const int b   = blockIdx.y;
    const int n0  = blockIdx.x * 64;
    const int tid = threadIdx.x;

    if (tid < 64) swb[tid] = g_wb[tid];
    for (int i = tid; i < 4096; i += 256) {
        int c = i >> 6, p = i & 63;
        sX[p*65 + c] = x[(b*CC + c)*NN + n0 + p];
    }
    __syncthreads();

    if (tid < 64) {
        const float* xr = sX + tid*65;
        float acc = 0.f;
        #pragma unroll 8
        for (int c = 0; c < 64; c++) acc += swb[c]*xr[c];
        g_beta[b*NN + n0 + tid] = acc;
    }
    for (int i = tid; i < 2048; i += 256) {
        int p = i >> 5, c0 = (i & 31)*2;
        float f0 = sX[p*65 + c0], f1 = sX[p*65 + c0 + 1];
        __half h0 = __float2half_rn(f0), h1 = __float2half_rn(f1);
        __half l0 = __float2half_rn(f0 - __half2float(h0));
        __half l1 = __float2half_rn(f1 - __half2float(h1));
        size_t base = (size_t)(b*NN + n0 + p)*KK + c0;
        *(__half2*)(g_xh + base) = __halves2half2(h0, h1);
        *(__half2*)(g_xl + base) = __halves2half2(l0, l1);
    }
}

// ---------------------------------------------------------------------------
// P2: kvea — fused phase, SMEM-staged weights, 32 px/block (grid 288).
// u' stored as single fp16 (2-term QK split consumes only u-hi).
// ---------------------------------------------------------------------------
__global__ void __launch_bounds__(256) kvea_kernel(
    const float* __restrict__ bn_w,  const float* __restrict__ bn_b,
    const float* __restrict__ bn_m,  const float* __restrict__ bn_v,
    const float* __restrict__ w_ea2, const float* __restrict__ b_ea2)
{
    extern __shared__ float sk[];
    const int b   = blockIdx.y;
    const int m0  = blockIdx.x * 32;
    const int tid = threadIdx.x;

    for (int i = tid; i < 1024; i += 256)
        *(float4*)(sk + KV_G + i*4) = *(const float4*)(g_G + i*4);
    for (int i = tid; i < 2048; i += 256)
        *(float4*)(sk + KV_W1T + i*4) = *(const float4*)(g_W1t + i*4);
    for (int i = tid; i < 2048; i += 256) {
        int c = i >> 5, p = i & 31;
        sk[KV_XP  + c*32 + p] = g_v  [(b*CC + c)*MM + m0 + p];
        sk[KV_C2P + c*32 + p] = g_c2p[(b*CC + c)*MM + m0 + p];
    }
    __syncthreads();

    const int ogi = (tid & 15) * 4;
    const int pg  = (tid >> 4) * 2;

    float hacc[4][2], tacc[4][2];
    #pragma unroll
    for (int i = 0; i < 4; i++) { hacc[i][0]=hacc[i][1]=tacc[i][0]=tacc[i][1]=0.f; }

    #pragma unroll 4
    for (int c = 0; c < 64; c++) {
        float4 wg = *(const float4*)(sk + KV_G   + c*64 + ogi);
        float4 w1 = *(const float4*)(sk + KV_W1T + c*64 + ogi);
        float x0 = sk[KV_XP  + c*32 + pg], x1 = sk[KV_XP  + c*32 + pg + 1];
        float c0 = sk[KV_C2P + c*32 + pg], c1 = sk[KV_C2P + c*32 + pg + 1];
        tacc[0][0] += wg.x*x0; tacc[1][0] += wg.y*x0; tacc[2][0] += wg.z*x0; tacc[3][0] += wg.w*x0;
        tacc[0][1] += wg.x*x1; tacc[1][1] += wg.y*x1; tacc[2][1] += wg.z*x1; tacc[3][1] += wg.w*x1;
        hacc[0][0] += w1.x*c0; hacc[1][0] += w1.y*c0; hacc[2][0] += w1.z*c0; hacc[3][0] += w1.w*c0;
        hacc[0][1] += w1.x*c1; hacc[1][1] += w1.y*c1; hacc[2][1] += w1.z*c1; hacc[3][1] += w1.w*c1;
    }
    #pragma unroll 4
    for (int c = 0; c < 64; c++) {
        float4 w1 = *(const float4*)(sk + KV_W1T + (64+c)*64 + ogi);
        float x0 = sk[KV_XP + c*32 + pg], x1 = sk[KV_XP + c*32 + pg + 1];
        hacc[0][0] += w1.x*x0; hacc[1][0] += w1.y*x0; hacc[2][0] += w1.z*x0; hacc[3][0] += w1.w*x0;
        hacc[0][1] += w1.x*x1; hacc[1][1] += w1.y*x1; hacc[2][1] += w1.z*x1; hacc[3][1] += w1.w*x1;
    }

    float pea0 = 0.f, pea1 = 0.f, pal0 = 0.f, pal1 = 0.f;
    #pragma unroll
    for (int oi = 0; oi < 4; oi++) {
        int o = ogi + oi;
        float scale = bn_w[o] * rsqrtf(bn_v[o] + 1e-5f);
        float mo = bn_m[o], bo = bn_b[o], w2 = w_ea2[o];
        float h0 = fmaxf((hacc[oi][0] - mo)*scale + bo, 0.f);
        float h1 = fmaxf((hacc[oi][1] - mo)*scale + bo, 0.f);
        pea0 += w2*h0; pea1 += w2*h1;
        float wbv = g_wb[o];
        pal0 += wbv * sk[KV_XP + o*32 + pg];
        pal1 += wbv * sk[KV_XP + o*32 + pg + 1];
    }
    #pragma unroll
    for (int off = 1; off < 16; off <<= 1) {
        pea0 += __shfl_xor_sync(0xffffffffu, pea0, off);
        pea1 += __shfl_xor_sync(0xffffffffu, pea1, off);
        pal0 += __shfl_xor_sync(0xffffffffu, pal0, off);
        pal1 += __shfl_xor_sync(0xffffffffu, pal1, off);
    }
    if ((tid & 15) == 0) {
        float bb = g_bb[0], be = b_ea2[0];
        float ea0 = 1.f / (1.f + __expf(-(pea0 + be)));
        float ea1 = 1.f / (1.f + __expf(-(pea1 + be)));
        sk[KV_EA + pg]     = ea0;
        sk[KV_EA + pg + 1] = ea1;
        g_eam[b*MM + m0 + pg    ] = ea0;
        g_eam[b*MM + m0 + pg + 1] = ea1;
        g_cm [b*MM + m0 + pg    ] = ea0 * (pal0 + bb);
        g_cm [b*MM + m0 + pg + 1] = ea1 * (pal1 + bb);
    }
    __syncthreads();

    // u' = ea * t, single fp16, store d-contiguous
    #pragma unroll
    for (int pi = 0; pi < 2; pi++) {
        float ea = sk[KV_EA + pg + pi];
        __half h0 = __float2half_rn(tacc[0][pi]*ea);
        __half h1 = __float2half_rn(tacc[1][pi]*ea);
        __half h2 = __float2half_rn(tacc[2][pi]*ea);
        __half h3 = __float2half_rn(tacc[3][pi]*ea);
        size_t base = (size_t)(b*MM + m0 + pg + pi)*KK + ogi;
        __half2 hh0 = __halves2half2(h0, h1), hh1 = __halves2half2(h2, h3);
        *(uint2*)(g_uh + base) = make_uint2(*(uint32_t*)&hh0, *(uint32_t*)&hh1);
    }
}

// ---------------------------------------------------------------------------
// A: flash attention on x vs u', cp.async double-buffered tiles.
// QK: 2-term split (xh + xl) x uh. PV: single fp16, P in registers.
// logit = x.u' + cm_col + beta_row*ea_col.
// ---------------------------------------------------------------------------
__global__ void __launch_bounds__(256, 2) attn_kernel(
    const float* __restrict__ x, const float* __restrict__ gamma,
    float* __restrict__ out)
{
    extern __shared__ float sm[];
    const uint32_t sb = smem_u32(sm);
    char* smc = (char*)sm;

    const int b    = blockIdx.y;
    const int n0   = blockIdx.x * 128;
    const int tid  = threadIdx.x;
    const int lane = tid & 31;
    const int warp = tid >> 5;
    const int rbase = warp * 16;

    const int lrow  = lane & 15;
    const int khalf = lane >> 4;
    const int gid   = lane >> 2;
    const int colb  = 2 * (lane & 3);
    const int prow0 = rbase + gid;
    const int arow  = rbase + lrow;

    const float g = gamma[0];

    // ---- load X block (pre-split) + beta ----------------------------------
    for (int i = tid; i < 1024; i += 256) {
        int r = i >> 3, u = i & 7;
        size_t gbase = (size_t)(b*NN + n0 + r)*KK + u*8;
        int soff = r*128 + ((u ^ (r&7))<<4);
        *(uint4*)(smc + B_XHI + soff) = *(const uint4*)(g_xh + gbase);
        *(uint4*)(smc + B_XLO + soff) = *(const uint4*)(g_xl + gbase);
    }
    if (tid < 32) *(uint4*)(smc + B_BETA + tid*16) =
        *(const uint4*)(g_beta + b*NN + n0 + tid*4);
    __syncthreads();
    const float beta0 = *(float*)(smc + B_BETA + prow0*4);
    const float beta1 = *(float*)(smc + B_BETA + (prow0+8)*4);

    // ---- prologue: async-load tile 0 into stage 0 -------------------------
    {
        const int mb = 0, s = 0;
        for (int i = tid; i < 512; i += 256) {
            int j = i >> 3, u = i & 7;
            int koff = j*128 + ((u ^ (j&7))<<4);
            size_t kb = (size_t)(b*MM + mb + j)*KK + u*8;
            cpa16(sb + B_ST(s) + ST_UH + koff, g_uh + kb);
            size_t vb = (size_t)(b*CC + j)*MM + mb + u*8;
            cpa16(sb + B_ST(s) + ST_VS + koff, g_vh + vb);
        }
        if (tid < 16)      cpa16(sb + B_ST(s) + ST_CM  + tid*16,      g_cm  + b*MM + mb + tid*4);
        else if (tid < 32) cpa16(sb + B_ST(s) + ST_EAM + (tid-16)*16, g_eam + b*MM + mb + (tid-16)*4);
        CPA_COMMIT();
    }

    float m0 = -1e30f, m1 = -1e30f, l0 = 0.f, l1 = 0.f;
    float O[8][4];
    #pragma unroll
    for (int nc = 0; nc < 8; nc++)
        #pragma unroll
        for (int j = 0; j < 4; j++) O[nc][j] = 0.f;

    for (int t = 0; t < MM/64; t++) {
        const int cur = t & 1;
        CPA_WAIT0();
        __syncthreads();   // tile t landed AND all warps done with stage cur

        if (t + 1 < MM/64) {
            const int mb2 = (t+1) * 64, s = cur ^ 1;
            for (int i = tid; i < 512; i += 256) {
                int j = i >> 3, u = i & 7;
                int koff = j*128 + ((u ^ (j&7))<<4);
                size_t kb = (size_t)(b*MM + mb2 + j)*KK + u*8;
                cpa16(sb + B_ST(s) + ST_UH + koff, g_uh + kb);
                size_t vb = (size_t)(b*CC + j)*MM + mb2 + u*8;
                cpa16(sb + B_ST(s) + ST_VS + koff, g_vh + vb);
            }
            if (tid < 16)      cpa16(sb + B_ST(s) + ST_CM  + tid*16,      g_cm  + b*MM + mb2 + tid*4);
            else if (tid < 32) cpa16(sb + B_ST(s) + ST_EAM + (tid-16)*16, g_eam + b*MM + mb2 + (tid-16)*4);
            CPA_COMMIT();
        }

        const uint32_t sbK = sb + B_ST(cur);
        char* stc = smc + B_ST(cur);

        // ---- S = X U'^T (2-term fp16 split: (xh + xl) * uh) ---------------
        float S[8][4];
        #pragma unroll
        for (int nc = 0; nc < 8; nc++)
            #pragma unroll
            for (int j = 0; j < 4; j++) S[nc][j] = 0.f;

        #pragma unroll
        for (int kc = 0; kc < 4; kc++) {
            const int unit = kc*2 + khalf;
            uint32_t ah[4], al[4];
            uint32_t aoff = arow*128 + (((unit ^ (arow&7)))<<4);
            ldm4(ah, sb + B_XHI + aoff);
            ldm4(al, sb + B_XLO + aoff);
            #pragma unroll
            for (int nc2 = 0; nc2 < 4; nc2++) {
                int key = nc2*16 + lrow;
                uint32_t boff = key*128 + (((unit ^ (key&7)))<<4);
                uint32_t bh[4];
                ldm4(bh, sbK + ST_UH + boff);
                mma16(S[nc2*2],   ah, bh[0], bh[2]);
                mma16(S[nc2*2+1], ah, bh[1], bh[3]);
                mma16(S[nc2*2],   al, bh[0], bh[2]);
                mma16(S[nc2*2+1], al, bh[1], bh[3]);
            }
        }

        // ---- bias terms: + cm_col + beta_row*ea_col -----------------------
        #pragma unroll
        for (int nc = 0; nc < 8; nc++) {
            float2 cm2 = *(float2*)(stc + ST_CM  + (nc*8 + colb)*4);
            float2 em2 = *(float2*)(stc + ST_EAM + (nc*8 + colb)*4);
            S[nc][0] += cm2.x + beta0*em2.x;
            S[nc][1] += cm2.y + beta0*em2.y;
            S[nc][2] += cm2.x + beta1*em2.x;
            S[nc][3] += cm2.y + beta1*em2.y;
        }

        // ---- online softmax ----------------------------------------------
        float rm0 = -1e30f, rm1 = -1e30f;
        #pragma unroll
        for (int nc = 0; nc < 8; nc++) {
            rm0 = fmaxf(rm0, fmaxf(S[nc][0], S[nc][1]));
            rm1 = fmaxf(rm1, fmaxf(S[nc][2], S[nc][3]));
        }
        rm0 = fmaxf(rm0, __shfl_xor_sync(0xffffffffu, rm0, 1));
        rm0 = fmaxf(rm0, __shfl_xor_sync(0xffffffffu, rm0, 2));
        rm1 = fmaxf(rm1, __shfl_xor_sync(0xffffffffu, rm1, 1));
        rm1 = fmaxf(rm1, __shfl_xor_sync(0xffffffffu, rm1, 2));
        float mn0 = fmaxf(m0, rm0), mn1 = fmaxf(m1, rm1);
        float a0 = __expf(m0 - mn0), a1 = __expf(m1 - mn1);
        m0 = mn0; m1 = mn1;
        float s0 = 0.f, s1 = 0.f;
        #pragma unroll
        for (int nc = 0; nc < 8; nc++) {
            S[nc][0] = __expf(S[nc][0] - mn0); s0 += S[nc][0];
            S[nc][1] = __expf(S[nc][1] - mn0); s0 += S[nc][1];
            S[nc][2] = __expf(S[nc][2] - mn1); s1 += S[nc][2];
            S[nc][3] = __expf(S[nc][3] - mn1); s1 += S[nc][3];
        }
        s0 += __shfl_xor_sync(0xffffffffu, s0, 1);
        s0 += __shfl_xor_sync(0xffffffffu, s0, 2);
        s1 += __shfl_xor_sync(0xffffffffu, s1, 1);
        s1 += __shfl_xor_sync(0xffffffffu, s1, 2);
        l0 = l0*a0 + s0;
        l1 = l1*a1 + s1;
        #pragma unroll
        for (int nc = 0; nc < 8; nc++) {
            O[nc][0] *= a0; O[nc][1] *= a0;
            O[nc][2] *= a1; O[nc][3] *= a1;
        }

        // ---- pack P into A-fragments (registers) --------------------------
        uint32_t pk[16];
        #pragma unroll
        for (int nc = 0; nc < 8; nc++) {
            pk[nc*2    ] = pack_h2(S[nc][0], S[nc][1]);
            pk[nc*2 + 1] = pack_h2(S[nc][2], S[nc][3]);
        }

        // ---- O += P V^T ---------------------------------------------------
        #pragma unroll
        for (int kc2 = 0; kc2 < 4; kc2++) {
            const int unit = kc2*2 + khalf;
            const uint32_t* a = pk + kc2*4;
            #pragma unroll
            for (int nc2 = 0; nc2 < 4; nc2++) {
                int ch = nc2*16 + lrow;
                uint32_t boff = ch*128 + (((unit ^ (ch&7)))<<4);
                uint32_t bv[4];
                ldm4(bv, sbK + ST_VS + boff);
                mma16(O[nc2*2],   a, bv[0], bv[2]);
                mma16(O[nc2*2+1], a, bv[1], bv[3]);
            }
        }
    }

    // ---- finalize ---------------------------------------------------------
    float inv0 = 1.f / l0, inv1 = 1.f / l1;
    #pragma unroll
    for (int nc = 0; nc < 8; nc++) {
        O[nc][0] *= inv0; O[nc][1] *= inv0;
        O[nc][2] *= inv1; O[nc][3] *= inv1;
    }

    __syncthreads();
    float* Ost = sm;   // [64 ch][128 row] fp32 (32 KB), aliases X regions
    #pragma unroll
    for (int nc = 0; nc < 8; nc++) {
        int c0 = nc*8 + colb;
        Ost[(c0    )*128 + prow0    ] = O[nc][0];
        Ost[(c0 + 1)*128 + prow0    ] = O[nc][1];
        Ost[(c0    )*128 + prow0 + 8] = O[nc][2];
        Ost[(c0 + 1)*128 + prow0 + 8] = O[nc][3];
    }
    __syncthreads();
    for (int i = tid; i < 8192; i += 256) {
        int c = i >> 7, r = i & 127;
        int gi = (b*CC + c)*NN + n0 + r;
        out[gi] = g * Ost[c*128 + r] + x[gi];
    }
}

// ---------------------------------------------------------------------------
extern "C" void kernel_launch(void* const* d_in, const int* in_sizes, int n_in,
                              void* d_out, int out_size)
{
    const float* c2    = (const float*)d_in[0];
    const float* x     = (const float*)d_in[1];
    const float* w_ea1 = (const float*)d_in[2];
    const float* bn_w  = (const float*)d_in[3];
    const float* bn_b  = (const float*)d_in[4];
    const float* bn_m  = (const float*)d_in[5];
    const float* bn_v  = (const float*)d_in[6];
    const float* w_ea2 = (const float*)d_in[7];
    const float* b_ea2 = (const float*)d_in[8];
    const float* w_q   = (const float*)d_in[9];
    const float* b_q   = (const float*)d_in[10];
    const float* gamma = (const float*)d_in[11];
    float* out = (float*)d_out;

    cudaFuncSetAttribute(kvea_kernel, cudaFuncAttributeMaxDynamicSharedMemorySize, KVEA_SMEM_BYTES);
    cudaFuncSetAttribute(attn_kernel, cudaFuncAttributeMaxDynamicSharedMemorySize, ATTN_SMEM_BYTES);

    gmat_kernel<<<1, 256>>>(w_q, b_q, w_ea1);
    pool_kernel<<<(BB*CC*MM + 255)/256, 256>>>(x, c2);
    xsplit_kernel<<<dim3(NN/64, BB), 256>>>(x);
    kvea_kernel<<<dim3(MM/32, BB), 256, KVEA_SMEM_BYTES>>>(bn_w, bn_b, bn_m, bn_v, w_ea2, b_ea2);
    attn_kernel<<<dim3(NN/128, BB), 256, ATTN_SMEM_BYTES>>>(x, gamma, out);
}